// round 3
// baseline (speedup 1.0000x reference)
#include <cuda_runtime.h>

// PairwisePotential1: out[b,c,h,w] = w1[c,hw] * (first/9) + w2[c,hw] * ((4+4*sqrt(2))/9)
// first = sum_{i,j in 0..2} exp(-0.5*(xp[h][w] - xp[h+i][w+j])^2 - 0.5*d(i,j))
// xp = zero-padded (1 each side) 130x130 plane; d(i,j) = sqrt(a_i^2 + a_j^2), a_0=0, a_1=a_2=1.
// (i,j)=(0,0) term is exactly 1. 4 terms have d=1, 4 terms have d=sqrt(2).

constexpr int S       = 128;
constexpr int C       = 64;
constexpr int TILE_H  = 8;             // output rows per CTA
constexpr int SM_ROWS = TILE_H + 2;    // 10 padded rows
constexpr int SM_COLS = 132;           // 130 used + pad
constexpr int NTHREADS = 256;

// -0.5 * log2(e)
#define KH  (-0.72134752044448170368f)
// -0.5 * 1 * log2(e)
#define CD1 (-0.72134752044448170368f)
// -0.5 * sqrt(2) * log2(e)
#define CD2 (-1.02013364214765880189f)
// (4 + 4*sqrt(2)) / 9
#define SEC9 (1.07298380546472528f)

__device__ __forceinline__ float ex2_approx(float a) {
    float r;
    asm("ex2.approx.ftz.f32 %0, %1;" : "=f"(r) : "f"(a));
    return r;
}

__device__ __forceinline__ float term(float c, float n, float cd) {
    float u = c - n;
    float arg = fmaf(u * KH, u, cd);
    return ex2_approx(arg);
}

__global__ __launch_bounds__(NTHREADS)
void pairwise_kernel(const float* __restrict__ x,
                     const float* __restrict__ w1,
                     const float* __restrict__ w2,
                     float* __restrict__ out) {
    __shared__ float sm[SM_ROWS][SM_COLS];

    const int b     = blockIdx.x;          // batch fastest -> w1/w2 L2 reuse across b
    const int ty    = blockIdx.y;          // tile row index (0..15)
    const int c     = blockIdx.z;          // channel
    const int hbase = ty * TILE_H;         // base padded-row of this tile

    const float* xplane = x + ((size_t)(b * C + c)) * (S * S);

    // Load padded tile: xp rows [hbase, hbase+9], cols [0, 129].
    // xp[r][cc] = x[r-1][cc-1] if 1<=r<=128 && 1<=cc<=128, else 0.
    for (int idx = threadIdx.x; idx < SM_ROWS * 130; idx += NTHREADS) {
        int rr = idx / 130;
        int cc = idx - rr * 130;
        int gr = hbase + rr;
        float v = 0.0f;
        if (gr >= 1 && gr <= S && cc >= 1 && cc <= S)
            v = xplane[(gr - 1) * S + (cc - 1)];
        sm[rr][cc] = v;
    }
    __syncthreads();

    const int w   = threadIdx.x & 127;     // output column
    const int g   = threadIdx.x >> 7;      // 0..1 vertical group
    const int lr0 = g * 4;                 // first local output row (4 rows per thread)

    // Rolling 3x3 window over rows lr0..lr0+5, cols w..w+2
    float r0a = sm[lr0    ][w], r0b = sm[lr0    ][w + 1], r0c = sm[lr0    ][w + 2];
    float r1a = sm[lr0 + 1][w], r1b = sm[lr0 + 1][w + 1], r1c = sm[lr0 + 1][w + 2];
    float r2a = sm[lr0 + 2][w], r2b = sm[lr0 + 2][w + 1], r2c = sm[lr0 + 2][w + 2];

    const float* w1c = w1 + (size_t)c * (S * S);
    const float* w2c = w2 + (size_t)c * (S * S);
    float* outp = out + ((size_t)(b * C + c)) * (S * S);

    #pragma unroll
    for (int k = 0; k < 4; k++) {
        const float cv = r0a;              // center = window (0,0)
        // two accumulators for ILP; center term contributes exactly 1
        float s0 = 1.0f + term(cv, r0b, CD1);   // (0,1) d=1
        float s1 = term(cv, r0c, CD1);          // (0,2) d=1
        s0 += term(cv, r1a, CD1);               // (1,0) d=1
        s1 += term(cv, r2a, CD1);               // (2,0) d=1
        s0 += term(cv, r1b, CD2);               // (1,1) d=sqrt2
        s1 += term(cv, r1c, CD2);               // (1,2) d=sqrt2
        s0 += term(cv, r2b, CD2);               // (2,1) d=sqrt2
        s1 += term(cv, r2c, CD2);               // (2,2) d=sqrt2
        float first = s0 + s1;

        int h   = hbase + lr0 + k;
        int pix = h * S + w;
        float o = fmaf(w1c[pix], first * (1.0f / 9.0f), w2c[pix] * SEC9);
        outp[pix] = o;

        if (k < 3) {
            // shift window down one row
            r0a = r1a; r0b = r1b; r0c = r1c;
            r1a = r2a; r1b = r2b; r1c = r2c;
            int nr = lr0 + k + 3;              // max 9, within SM_ROWS
            r2a = sm[nr][w]; r2b = sm[nr][w + 1]; r2c = sm[nr][w + 2];
        }
    }
}

extern "C" void kernel_launch(void* const* d_in, const int* in_sizes, int n_in,
                              void* d_out, int out_size) {
    const float* x  = (const float*)d_in[0];
    const float* w1 = (const float*)d_in[1];
    const float* w2 = (const float*)d_in[2];
    float* out = (float*)d_out;

    int B = in_sizes[0] / (C * S * S);     // 16
    dim3 grid(B, S / TILE_H, C);           // b fastest -> w1/w2 reuse in L2
    pairwise_kernel<<<grid, NTHREADS>>>(x, w1, w2, out);
}

// round 4
// speedup vs baseline: 1.0322x; 1.0322x over previous
#include <cuda_runtime.h>

// PairwisePotential1 on sm_103a.
// out[b,c,h,w] = w1[c,hw]*(first/9) + w2[c,hw]*((4+4*sqrt2)/9)
// first = 1 + sum over 8 offsets (i,j) in {0,1,2}^2 \ (0,0) of
//         exp(-0.5*(xp[h][w]-xp[h+i][w+j])^2 - 0.5*d(i,j)),
// d = 1 for (0,1),(0,2),(1,0),(2,0);  d = sqrt(2) for (1,1),(1,2),(2,1),(2,2).
// Packed f32x2 FP32 for argument math (2 px/instr), scalar ex2.approx (MUFU floor).

constexpr int S        = 128;
constexpr int C        = 64;
constexpr int TILE_H   = 8;              // one output row per warp; 8 warps per CTA
constexpr int SM_ROWS  = TILE_H + 2;
constexpr int SM_COLS  = 132;            // 130 used; 132 keeps 16B row alignment
constexpr int NTHREADS = 256;

#define KH    (-0.72134752044448170368f)   // -0.5*log2(e)
#define CD1   (-0.72134752044448170368f)   // -0.5*1*log2(e)
#define CD2   (-1.02013364214765880189f)   // -0.5*sqrt(2)*log2(e)
#define SEC9  (1.07298380546472528f)       // (4+4*sqrt2)/9
#define NINTH (0.11111111111111111111f)

typedef unsigned long long u64t;

__device__ __forceinline__ float ex2a(float a) {
    float r; asm("ex2.approx.ftz.f32 %0, %1;" : "=f"(r) : "f"(a)); return r;
}
__device__ __forceinline__ u64t pk2(float lo, float hi) {
    u64t r; asm("mov.b64 %0, {%1, %2};" : "=l"(r) : "f"(lo), "f"(hi)); return r;
}
__device__ __forceinline__ u64t fma2(u64t a, u64t b, u64t c) {
    u64t d; asm("fma.rn.f32x2 %0, %1, %2, %3;" : "=l"(d) : "l"(a), "l"(b), "l"(c)); return d;
}
__device__ __forceinline__ u64t mul2(u64t a, u64t b) {
    u64t d; asm("mul.rn.f32x2 %0, %1, %2;" : "=l"(d) : "l"(a), "l"(b)); return d;
}
__device__ __forceinline__ void up2(u64t v, float& lo, float& hi) {
    asm("mov.b64 {%0, %1}, %2;" : "=f"(lo), "=f"(hi) : "l"(v));
}

// One term-offset for a pixel PAIR: packed arg math, scalar ex2 + accumulate.
__device__ __forceinline__ void term2(u64t c2, u64t n2, u64t cd2, u64t kh2, u64t neg1,
                                      float& sl, float& sh) {
    u64t u   = fma2(n2, neg1, c2);   // c - n  (packed)
    u64t t   = mul2(u, kh2);         // KH*u
    u64t arg = fma2(t, u, cd2);      // KH*u^2 + cd
    float al, ah; up2(arg, al, ah);
    sl += ex2a(al);
    sh += ex2a(ah);
}

__global__ __launch_bounds__(NTHREADS)
void pairwise_kernel(const float* __restrict__ x,
                     const float* __restrict__ w1,
                     const float* __restrict__ w2,
                     float* __restrict__ out) {
    __shared__ float sm[SM_ROWS][SM_COLS];

    const int b     = blockIdx.x;        // batch fastest -> w1/w2 L2 reuse
    const int ty    = blockIdx.y;
    const int c     = blockIdx.z;
    const int hbase = ty * TILE_H;

    const float* xplane = x + ((size_t)(b * C + c)) * (S * S);

    // Load padded tile rows [hbase, hbase+9], cols [0,129]. xp[r][cc]=x[r-1][cc-1] in-bounds else 0.
    for (int idx = threadIdx.x; idx < SM_ROWS * 130; idx += NTHREADS) {
        int rr = idx / 130;
        int cc = idx - rr * 130;
        int gr = hbase + rr;
        float v = 0.0f;
        if (gr >= 1 && gr <= S && cc >= 1 && cc <= S)
            v = xplane[(gr - 1) * S + (cc - 1)];
        sm[rr][cc] = v;
    }
    __syncthreads();

    const int t  = threadIdx.x & 31;     // column group (4 px each) -> warp = one row
    const int lr = threadIdx.x >> 5;     // local output row 0..7
    const int w  = t * 4;                // output columns w..w+3

    const u64t neg1 = pk2(-1.0f, -1.0f);
    const u64t kh2  = pk2(KH, KH);
    const u64t cd1  = pk2(CD1, CD1);
    const u64t cd2  = pk2(CD2, CD2);

    // Window: rows lr..lr+2, cols w..w+5. Aligned vector LDS.
    float4 a0 = *(const float4*)&sm[lr    ][w];
    float2 b0 = *(const float2*)&sm[lr    ][w + 4];
    float4 a1 = *(const float4*)&sm[lr + 1][w];
    float2 b1 = *(const float2*)&sm[lr + 1][w + 4];
    float4 a2 = *(const float4*)&sm[lr + 2][w];
    float2 b2 = *(const float2*)&sm[lr + 2][w + 4];

    const u64t cA = pk2(a0.x, a0.y);     // centers for pixels w, w+1
    const u64t cB = pk2(a0.z, a0.w);     // centers for pixels w+2, w+3

    float s0 = 0.f, s1 = 0.f, s2 = 0.f, s3 = 0.f;

    // row i=0: offsets (0,1) d=1, (0,2) d=1
    term2(cA, pk2(a0.y, a0.z), cd1, kh2, neg1, s0, s1);
    term2(cB, pk2(a0.w, b0.x), cd1, kh2, neg1, s2, s3);
    term2(cA, pk2(a0.z, a0.w), cd1, kh2, neg1, s0, s1);
    term2(cB, pk2(b0.x, b0.y), cd1, kh2, neg1, s2, s3);
    // row i=1: (1,0) d=1, (1,1) d=sqrt2, (1,2) d=sqrt2
    term2(cA, pk2(a1.x, a1.y), cd1, kh2, neg1, s0, s1);
    term2(cB, pk2(a1.z, a1.w), cd1, kh2, neg1, s2, s3);
    term2(cA, pk2(a1.y, a1.z), cd2, kh2, neg1, s0, s1);
    term2(cB, pk2(a1.w, b1.x), cd2, kh2, neg1, s2, s3);
    term2(cA, pk2(a1.z, a1.w), cd2, kh2, neg1, s0, s1);
    term2(cB, pk2(b1.x, b1.y), cd2, kh2, neg1, s2, s3);
    // row i=2: (2,0) d=1, (2,1) d=sqrt2, (2,2) d=sqrt2
    term2(cA, pk2(a2.x, a2.y), cd1, kh2, neg1, s0, s1);
    term2(cB, pk2(a2.z, a2.w), cd1, kh2, neg1, s2, s3);
    term2(cA, pk2(a2.y, a2.z), cd2, kh2, neg1, s0, s1);
    term2(cB, pk2(a2.w, b2.x), cd2, kh2, neg1, s2, s3);
    term2(cA, pk2(a2.z, a2.w), cd2, kh2, neg1, s0, s1);
    term2(cB, pk2(b2.x, b2.y), cd2, kh2, neg1, s2, s3);

    // Epilogue: first = s+1; o = w1*first/9 + w2*SEC9, fully vectorized I/O.
    const int h   = hbase + lr;
    const int pix = h * S + w;
    const float4 W1 = *(const float4*)(w1 + (size_t)c * (S * S) + pix);
    const float4 W2 = *(const float4*)(w2 + (size_t)c * (S * S) + pix);
    float4 o;
    o.x = fmaf(W1.x, fmaf(s0, NINTH, NINTH), W2.x * SEC9);
    o.y = fmaf(W1.y, fmaf(s1, NINTH, NINTH), W2.y * SEC9);
    o.z = fmaf(W1.z, fmaf(s2, NINTH, NINTH), W2.z * SEC9);
    o.w = fmaf(W1.w, fmaf(s3, NINTH, NINTH), W2.w * SEC9);
    *(float4*)(out + ((size_t)(b * C + c)) * (S * S) + pix) = o;
}

extern "C" void kernel_launch(void* const* d_in, const int* in_sizes, int n_in,
                              void* d_out, int out_size) {
    const float* x  = (const float*)d_in[0];
    const float* w1 = (const float*)d_in[1];
    const float* w2 = (const float*)d_in[2];
    float* out = (float*)d_out;

    int B = in_sizes[0] / (C * S * S);   // 16
    dim3 grid(B, S / TILE_H, C);
    pairwise_kernel<<<grid, NTHREADS>>>(x, w1, w2, out);
}

// round 5
// speedup vs baseline: 1.8586x; 1.8005x over previous
#include <cuda_runtime.h>

// PairwisePotential1 on sm_103a — warp-per-row, shuffle-halo, no smem/barrier.
// out[b,c,h,w] = w1[c,hw]*(first/9) + w2[c,hw]*((4+4*sqrt2)/9)
// first = 1 + sum over (i,j) in {0,1,2}^2\{0,0} of exp(-0.5*(xp[h][w]-xp[h+i][w+j])^2 - 0.5*d)
// xp = zero-pad(x,1); window rows h..h+2 (padded) = unpadded rows h-1..h+1,
// padded cols w..w+5 for 4 pixels = unpadded cols w-1..w+4.
// d=1 for (0,1),(0,2),(1,0),(2,0);  d=sqrt2 for (1,1),(1,2),(2,1),(2,2).

constexpr int S = 128;
constexpr int C = 64;

#define KH    (-0.72134752044448170368f)   // -0.5*log2(e)
#define CD1   (-0.72134752044448170368f)   // -0.5*1*log2(e)
#define CD2   (-1.02013364214765880189f)   // -0.5*sqrt(2)*log2(e)
#define SEC9  (1.07298380546472528f)       // (4+4*sqrt2)/9
#define NINTH (0.11111111111111111111f)

__device__ __forceinline__ float ex2a(float a) {
    float r; asm("ex2.approx.ftz.f32 %0, %1;" : "=f"(r) : "f"(a)); return r;
}

// exp(-0.5*(c-n)^2 - 0.5*d) = 2^( (KH*u)*u + cd ),  u = c-n
__device__ __forceinline__ float term(float c, float n, float cd) {
    float u = c - n;
    return ex2a(fmaf(u * KH, u, cd));
}

__global__ __launch_bounds__(256)
void pairwise_kernel(const float* __restrict__ x,
                     const float* __restrict__ w1,
                     const float* __restrict__ w2,
                     float* __restrict__ out) {
    const int b  = blockIdx.x;             // batch fastest -> w1/w2 L2 reuse
    const int ty = blockIdx.y;
    const int c  = blockIdx.z;
    const int t  = threadIdx.x & 31;       // lane -> 4-pixel column group
    const int wd = threadIdx.x >> 5;       // warp -> output row within tile
    const int h  = ty * 8 + wd;            // output row 0..127
    const int w4 = t * 4;                  // output cols w4..w4+3

    const size_t plane = (size_t)(b * C + c) * (S * S);
    const int    pix   = h * S + w4;

    // Hoist w1/w2 loads: independent, overlap with everything below.
    const float4 W1 = *(const float4*)(w1 + (size_t)c * (S * S) + pix);
    const float4 W2 = *(const float4*)(w2 + (size_t)c * (S * S) + pix);

    // Three x rows: unpadded h-1, h, h+1 (warp-uniform bounds -> zero rows).
    const float* xr = x + plane + (h - 1) * S + w4;
    float4 v0 = make_float4(0.f, 0.f, 0.f, 0.f);
    float4 v1 = make_float4(0.f, 0.f, 0.f, 0.f);
    float4 v2 = make_float4(0.f, 0.f, 0.f, 0.f);
    if (h >= 1)     v0 = *(const float4*)(xr);
    v1 = *(const float4*)(xr + S);         // row h always in range
    if (h + 1 < S)  v2 = *(const float4*)(xr + 2 * S);

    // Halo via shuffle: L = lane-1's .w (padded col w4), R = lane+1's .x (padded col w4+5).
    float L0 = __shfl_up_sync(0xffffffffu, v0.w, 1);
    float L1 = __shfl_up_sync(0xffffffffu, v1.w, 1);
    float L2 = __shfl_up_sync(0xffffffffu, v2.w, 1);
    float R0 = __shfl_down_sync(0xffffffffu, v0.x, 1);
    float R1 = __shfl_down_sync(0xffffffffu, v1.x, 1);
    float R2 = __shfl_down_sync(0xffffffffu, v2.x, 1);
    if (t == 0)  { L0 = 0.f; L1 = 0.f; L2 = 0.f; }
    if (t == 31) { R0 = 0.f; R1 = 0.f; R2 = 0.f; }

    // s[r][0..5] = padded cols w4..w4+5 of padded rows h, h+1, h+2.
    const float s0[6] = {L0, v0.x, v0.y, v0.z, v0.w, R0};
    const float s1[6] = {L1, v1.x, v1.y, v1.z, v1.w, R1};
    const float s2[6] = {L2, v2.x, v2.y, v2.z, v2.w, R2};

    float f[4];
    #pragma unroll
    for (int k = 0; k < 4; k++) {
        const float cv = s0[k];            // center = window (0,0) = padded (h, w4+k)
        // two accumulator chains for ILP
        float a0, a1;
        a0  = term(cv, s0[k + 1], CD1);    // (0,1) d=1
        a1  = term(cv, s0[k + 2], CD1);    // (0,2) d=1
        a0 += term(cv, s1[k],     CD1);    // (1,0) d=1
        a1 += term(cv, s1[k + 1], CD2);    // (1,1) d=sqrt2
        a0 += term(cv, s1[k + 2], CD2);    // (1,2) d=sqrt2
        a1 += term(cv, s2[k],     CD1);    // (2,0) d=1
        a0 += term(cv, s2[k + 1], CD2);    // (2,1) d=sqrt2
        a1 += term(cv, s2[k + 2], CD2);    // (2,2) d=sqrt2
        f[k] = a0 + a1;                    // first = f[k] + 1 (center term)
    }

    float4 o;
    o.x = fmaf(W1.x, fmaf(f[0], NINTH, NINTH), W2.x * SEC9);
    o.y = fmaf(W1.y, fmaf(f[1], NINTH, NINTH), W2.y * SEC9);
    o.z = fmaf(W1.z, fmaf(f[2], NINTH, NINTH), W2.z * SEC9);
    o.w = fmaf(W1.w, fmaf(f[3], NINTH, NINTH), W2.w * SEC9);
    *(float4*)(out + plane + pix) = o;
}

extern "C" void kernel_launch(void* const* d_in, const int* in_sizes, int n_in,
                              void* d_out, int out_size) {
    const float* x  = (const float*)d_in[0];
    const float* w1 = (const float*)d_in[1];
    const float* w2 = (const float*)d_in[2];
    float* out = (float*)d_out;

    int B = in_sizes[0] / (C * S * S);     // 16
    dim3 grid(B, S / 8, C);                // 8 rows (8 warps) per CTA
    pairwise_kernel<<<grid, 256>>>(x, w1, w2, out);
}

// round 6
// speedup vs baseline: 1.9580x; 1.0535x over previous
#include <cuda_runtime.h>

// PairwisePotential1 on sm_103a — warp-per-2-rows, shuffle halo, FFMA-imm term form.
// out[b,c,h,w] = w1[c,hw]*(first/9) + w2[c,hw]*((4+4*sqrt2)/9)
// first = 1 + sum_{(i,j) in {0,1,2}^2\{0,0}} exp(-0.5*(xp[h][w]-xp[h+i][w+j])^2 - 0.5*d(i,j))
// xp = zero-pad(x,1). Center of output (h,w) is xp[h][w] = x[h-1][w-1].
// d=1 for (0,1),(0,2),(1,0),(2,0);  d=sqrt2 for (1,1),(1,2),(2,1),(2,2).

constexpr int S = 128;
constexpr int C = 64;

#define KH    (-0.72134752044448170368f)   // -0.5*log2(e)
#define CD1   (-0.72134752044448170368f)   // -0.5*1*log2(e)
#define CD2   (-1.02013364214765880189f)   // -0.5*sqrt(2)*log2(e)
#define SEC9  (1.07298380546472528f)       // (4+4*sqrt2)/9
#define NINTH (0.11111111111111111111f)

__device__ __forceinline__ float ex2a(float a) {
    float r; asm("ex2.approx.ftz.f32 %0, %1;" : "=f"(r) : "f"(a)); return r;
}

// t = u*u (FMUL rt2), arg = t*KH_imm + cd (FFMA-imm rt1)
__device__ __forceinline__ float term(float c, float n, float cd) {
    float u = c - n;
    float t = u * u;
    return ex2a(fmaf(t, KH, cd));
}

__global__ __launch_bounds__(256)
void pairwise_kernel(const float* __restrict__ x,
                     const float* __restrict__ w1,
                     const float* __restrict__ w2,
                     float* __restrict__ out) {
    const int b  = blockIdx.x;             // batch fastest -> w1/w2 L2 reuse
    const int ty = blockIdx.y;             // 0..7 (16 rows per CTA)
    const int c  = blockIdx.z;
    const int t  = threadIdx.x & 31;       // lane -> 4-pixel column group
    const int wd = threadIdx.x >> 5;       // warp -> 2-row group within tile
    const int h  = ty * 16 + wd * 2;       // first output row (0,2,...,126)
    const int w4 = t * 4;                  // output cols w4..w4+3

    const size_t plane = (size_t)(b * C + c) * (S * S);
    const int    pix0  = h * S + w4;

    // Hoist w1/w2 loads (2 rows each) — independent of x path.
    const float* w1p = w1 + (size_t)c * (S * S) + pix0;
    const float* w2p = w2 + (size_t)c * (S * S) + pix0;
    const float4 W1a = *(const float4*)(w1p);
    const float4 W1b = *(const float4*)(w1p + S);
    const float4 W2a = *(const float4*)(w2p);
    const float4 W2b = *(const float4*)(w2p + S);

    // Four x rows: unpadded h-1 .. h+2 (warp-uniform bounds -> zero rows).
    const float* xr = x + plane + (h - 1) * S + w4;
    float4 v0 = make_float4(0.f, 0.f, 0.f, 0.f);
    float4 v3 = make_float4(0.f, 0.f, 0.f, 0.f);
    if (h >= 1)      v0 = *(const float4*)(xr);
    float4 v1 = *(const float4*)(xr + S);          // row h     (always in range)
    float4 v2 = *(const float4*)(xr + 2 * S);      // row h+1   (h+1 <= 127)
    if (h + 2 < S)   v3 = *(const float4*)(xr + 3 * S);

    // Halo via shuffle: L = lane-1's .w (padded col w4), R = lane+1's .x (padded col w4+5).
    float L0 = __shfl_up_sync(0xffffffffu, v0.w, 1);
    float L1 = __shfl_up_sync(0xffffffffu, v1.w, 1);
    float L2 = __shfl_up_sync(0xffffffffu, v2.w, 1);
    float L3 = __shfl_up_sync(0xffffffffu, v3.w, 1);
    float R0 = __shfl_down_sync(0xffffffffu, v0.x, 1);
    float R1 = __shfl_down_sync(0xffffffffu, v1.x, 1);
    float R2 = __shfl_down_sync(0xffffffffu, v2.x, 1);
    float R3 = __shfl_down_sync(0xffffffffu, v3.x, 1);
    if (t == 0)  { L0 = 0.f; L1 = 0.f; L2 = 0.f; L3 = 0.f; }
    if (t == 31) { R0 = 0.f; R1 = 0.f; R2 = 0.f; R3 = 0.f; }

    // s{r}[0..5] = padded cols w4..w4+5 of padded rows h+r (r=0..3).
    const float s0[6] = {L0, v0.x, v0.y, v0.z, v0.w, R0};
    const float s1[6] = {L1, v1.x, v1.y, v1.z, v1.w, R1};
    const float s2[6] = {L2, v2.x, v2.y, v2.z, v2.w, R2};
    const float s3[6] = {L3, v3.x, v3.y, v3.z, v3.w, R3};

    float fA[4], fB[4];
    #pragma unroll
    for (int k = 0; k < 4; k++) {
        // --- output row h: center s0[k], neighbor rows s0,s1,s2 ---
        {
            const float cv = s0[k];
            float a0, a1;
            a0  = term(cv, s0[k + 1], CD1);
            a1  = term(cv, s0[k + 2], CD1);
            a0 += term(cv, s1[k],     CD1);
            a1 += term(cv, s1[k + 1], CD2);
            a0 += term(cv, s1[k + 2], CD2);
            a1 += term(cv, s2[k],     CD1);
            a0 += term(cv, s2[k + 1], CD2);
            a1 += term(cv, s2[k + 2], CD2);
            fA[k] = a0 + a1;
        }
        // --- output row h+1: center s1[k], neighbor rows s1,s2,s3 ---
        {
            const float cv = s1[k];
            float a0, a1;
            a0  = term(cv, s1[k + 1], CD1);
            a1  = term(cv, s1[k + 2], CD1);
            a0 += term(cv, s2[k],     CD1);
            a1 += term(cv, s2[k + 1], CD2);
            a0 += term(cv, s2[k + 2], CD2);
            a1 += term(cv, s3[k],     CD1);
            a0 += term(cv, s3[k + 1], CD2);
            a1 += term(cv, s3[k + 2], CD2);
            fB[k] = a0 + a1;
        }
    }

    float4 oa, ob;
    oa.x = fmaf(W1a.x, fmaf(fA[0], NINTH, NINTH), W2a.x * SEC9);
    oa.y = fmaf(W1a.y, fmaf(fA[1], NINTH, NINTH), W2a.y * SEC9);
    oa.z = fmaf(W1a.z, fmaf(fA[2], NINTH, NINTH), W2a.z * SEC9);
    oa.w = fmaf(W1a.w, fmaf(fA[3], NINTH, NINTH), W2a.w * SEC9);
    ob.x = fmaf(W1b.x, fmaf(fB[0], NINTH, NINTH), W2b.x * SEC9);
    ob.y = fmaf(W1b.y, fmaf(fB[1], NINTH, NINTH), W2b.y * SEC9);
    ob.z = fmaf(W1b.z, fmaf(fB[2], NINTH, NINTH), W2b.z * SEC9);
    ob.w = fmaf(W1b.w, fmaf(fB[3], NINTH, NINTH), W2b.w * SEC9);
    float* op = out + plane + pix0;
    *(float4*)(op)     = oa;
    *(float4*)(op + S) = ob;
}

extern "C" void kernel_launch(void* const* d_in, const int* in_sizes, int n_in,
                              void* d_out, int out_size) {
    const float* x  = (const float*)d_in[0];
    const float* w1 = (const float*)d_in[1];
    const float* w2 = (const float*)d_in[2];
    float* out = (float*)d_out;

    int B = in_sizes[0] / (C * S * S);     // 16
    dim3 grid(B, S / 16, C);               // 16 rows (8 warps x 2 rows) per CTA
    pairwise_kernel<<<grid, 256>>>(x, w1, w2, out);
}